// round 5
// baseline (speedup 1.0000x reference)
#include <cuda_runtime.h>
#include <cuda_bf16.h>
#include <math.h>
#include <stdint.h>

#define HW    16384
#define WIDTH 128
#define NB    8
#define CQKV  192

// ---------------- scratch (static device allocations; no cudaMalloc) --------
__device__ float g_qkv[NB * CQKV * HW];   // 100.7 MB
__device__ float g_d  [NB * CQKV * HW];   // 100.7 MB
__device__ float g_o  [NB * 128  * HW];   //  67.1 MB
__device__ float g_kvp[NB * 16 * 8 * 72];
__device__ float g_kv [NB * 16 * 72];

// ---------------- bf16 split helpers ----------------------------------------
__device__ __forceinline__ void bsplit(float x, float& h, float& l) {
    h = __bfloat162float(__float2bfloat16_rn(x));
    l = x - h;
}
__device__ __forceinline__ uint32_t bpack(float a, float b) {
    __nv_bfloat162 t = __floats2bfloat162_rn(a, b);   // .x = a, .y = b
    return *reinterpret_cast<uint32_t*>(&t);
}
__device__ __forceinline__ void mma_bf16(float c[4], const uint32_t a[4], const uint32_t b[2]) {
    asm volatile(
        "mma.sync.aligned.m16n8k16.row.col.f32.bf16.bf16.f32 "
        "{%0,%1,%2,%3}, {%4,%5,%6,%7}, {%8,%9}, {%0,%1,%2,%3};\n"
        : "+f"(c[0]), "+f"(c[1]), "+f"(c[2]), "+f"(c[3])
        : "r"(a[0]), "r"(a[1]), "r"(a[2]), "r"(a[3]), "r"(b[0]), "r"(b[1]));
}

// ============ bf16x3 pipelined HMMA GEMM: C[b](M x HW) = W(M x KTOT) * X[b] =
// Block tile 64(M) x 128(N), 128 threads = 4 warps, warp tile 32x64.
// Weights (A) pre-split hi/lo into smem once for the FULL K.
// B (activations) double-buffered: early LDG into regs, STS after MMA phase.
// Split terms ordered pass-wise (hh, hl, lh) to avoid accumulator RAW stalls.
// MODE 0: plain store. MODE 1: batchnorm affine on output row (channel).
template <int KTOT, int MODE>
__global__ void __launch_bounds__(128)
hgemm(const float* __restrict__ W,
      const float* __restrict__ X,
      float* __restrict__ C,
      int M,
      const float* __restrict__ gamma,
      const float* __restrict__ beta,
      const float* __restrict__ mean,
      const float* __restrict__ var)
{
    constexpr int KP   = KTOT / 2;        // k-pairs total
    constexpr int SA   = KP + 8;          // A pair-row stride (≡8 mod 32)
    constexpr int AW   = 64 * SA;         // words per A half
    constexpr int SB   = 136;             // B pair-row stride (128+8)
    constexpr int BSTH = 16 * SB;         // words per B half per stage (2176)
    constexpr int NKIT = KTOT / 32;

    extern __shared__ uint32_t sm[];
    uint32_t* Ah = sm;
    uint32_t* Al = sm + AW;
    // B stage s: hi at 2*AW + s*2*BSTH, lo at +BSTH

    const int tid  = threadIdx.x;
    const int lane = tid & 31;
    const int warp = tid >> 5;
    const int wm   = warp >> 1;
    const int wn   = warp & 1;
    const int g    = lane >> 2;
    const int tg   = lane & 3;

    const int m0 = blockIdx.y * 64;
    const int n0 = blockIdx.x * 128;
    const float* Xb = X + (size_t)blockIdx.z * KTOT * HW;
    float*       Cb = C + (size_t)blockIdx.z * M * HW;

    // ---- A: full-K weight tile, split once ----
    #pragma unroll 4
    for (int j = 0; j < KTOT / 8; j++) {
        int idx = tid + j * 128;
        int row = idx / (KTOT / 4);
        int k   = (idx % (KTOT / 4)) * 4;
        float4 v = *(const float4*)&W[(size_t)(m0 + row) * KTOT + k];
        float h0,l0,h1,l1,h2,l2,h3,l3;
        bsplit(v.x,h0,l0); bsplit(v.y,h1,l1); bsplit(v.z,h2,l2); bsplit(v.w,h3,l3);
        int o = row * SA + (k >> 1);
        Ah[o] = bpack(h0, h1); Ah[o + 1] = bpack(h2, h3);
        Al[o] = bpack(l0, l1); Al[o + 1] = bpack(l2, l3);
    }

    // ---- B loader role: thread owns k-pair row kpB, 16 cols at ngB*16 ----
    const int kpB = tid >> 3;             // 0..15
    const int ngB = tid & 7;              // 0..7
    const float* bbase = Xb + (size_t)(2 * kpB) * HW + n0 + ngB * 16;

    float4 sr0[4], sr1[4];                // staged raw rows (even k, odd k)
    {   // prologue: tile 0
        const float* p0 = bbase;
        const float* p1 = bbase + HW;
        #pragma unroll
        for (int q = 0; q < 4; q++) {
            sr0[q] = *(const float4*)(p0 + q * 4);
            sr1[q] = *(const float4*)(p1 + q * 4);
        }
    }
    {   // STS stage 0
        uint32_t* BH = sm + 2 * AW;
        uint32_t* BL = BH + BSTH;
        #pragma unroll
        for (int q = 0; q < 4; q++) {
            const float a[4] = {sr0[q].x, sr0[q].y, sr0[q].z, sr0[q].w};
            const float b[4] = {sr1[q].x, sr1[q].y, sr1[q].z, sr1[q].w};
            uint32_t hw[4], lw[4];
            #pragma unroll
            for (int jj = 0; jj < 4; jj++) {
                float ha, la, hb, lb;
                bsplit(a[jj], ha, la); bsplit(b[jj], hb, lb);
                hw[jj] = bpack(ha, hb); lw[jj] = bpack(la, lb);
            }
            int off = kpB * SB + ngB * 16 + q * 4;
            *(uint4*)&BH[off] = make_uint4(hw[0], hw[1], hw[2], hw[3]);
            *(uint4*)&BL[off] = make_uint4(lw[0], lw[1], lw[2], lw[3]);
        }
    }
    __syncthreads();

    float c[2][8][4] = {};

    for (int it = 0; it < NKIT; it++) {
        // ---- issue next tile's global loads early ----
        if (it + 1 < NKIT) {
            const float* p0 = bbase + (size_t)((it + 1) * 32) * HW;
            const float* p1 = p0 + HW;
            #pragma unroll
            for (int q = 0; q < 4; q++) {
                sr0[q] = *(const float4*)(p0 + q * 4);
                sr1[q] = *(const float4*)(p1 + q * 4);
            }
        }

        const uint32_t* BH = sm + 2 * AW + (it & 1) * 2 * BSTH;
        const uint32_t* BL = BH + BSTH;

        #pragma unroll
        for (int ks = 0; ks < 2; ks++) {
            const int kp0 = it * 16 + ks * 8;
            uint32_t ah[2][4], al[2][4];
            #pragma unroll
            for (int mt = 0; mt < 2; mt++) {
                int r = wm * 32 + mt * 16 + g;
                ah[mt][0] = Ah[r * SA + kp0 + tg];
                ah[mt][1] = Ah[(r + 8) * SA + kp0 + tg];
                ah[mt][2] = Ah[r * SA + kp0 + tg + 4];
                ah[mt][3] = Ah[(r + 8) * SA + kp0 + tg + 4];
                al[mt][0] = Al[r * SA + kp0 + tg];
                al[mt][1] = Al[(r + 8) * SA + kp0 + tg];
                al[mt][2] = Al[r * SA + kp0 + tg + 4];
                al[mt][3] = Al[(r + 8) * SA + kp0 + tg + 4];
            }
            uint32_t bh[8][2], bl[8][2];
            #pragma unroll
            for (int nt = 0; nt < 8; nt++) {
                int col = wn * 64 + nt * 8 + g;
                bh[nt][0] = BH[(ks * 8 + tg) * SB + col];
                bh[nt][1] = BH[(ks * 8 + tg + 4) * SB + col];
                bl[nt][0] = BL[(ks * 8 + tg) * SB + col];
                bl[nt][1] = BL[(ks * 8 + tg + 4) * SB + col];
            }
            // pass 1: hi*hi
            #pragma unroll
            for (int nt = 0; nt < 8; nt++)
                #pragma unroll
                for (int mt = 0; mt < 2; mt++) mma_bf16(c[mt][nt], ah[mt], bh[nt]);
            // pass 2: hi*lo
            #pragma unroll
            for (int nt = 0; nt < 8; nt++)
                #pragma unroll
                for (int mt = 0; mt < 2; mt++) mma_bf16(c[mt][nt], ah[mt], bl[nt]);
            // pass 3: lo*hi
            #pragma unroll
            for (int nt = 0; nt < 8; nt++)
                #pragma unroll
                for (int mt = 0; mt < 2; mt++) mma_bf16(c[mt][nt], al[mt], bh[nt]);
        }

        // ---- STS next stage ----
        if (it + 1 < NKIT) {
            uint32_t* WH = sm + 2 * AW + ((it + 1) & 1) * 2 * BSTH;
            uint32_t* WL = WH + BSTH;
            #pragma unroll
            for (int q = 0; q < 4; q++) {
                const float a[4] = {sr0[q].x, sr0[q].y, sr0[q].z, sr0[q].w};
                const float b[4] = {sr1[q].x, sr1[q].y, sr1[q].z, sr1[q].w};
                uint32_t hw[4], lw[4];
                #pragma unroll
                for (int jj = 0; jj < 4; jj++) {
                    float ha, la, hb, lb;
                    bsplit(a[jj], ha, la); bsplit(b[jj], hb, lb);
                    hw[jj] = bpack(ha, hb); lw[jj] = bpack(la, lb);
                }
                int off = kpB * SB + ngB * 16 + q * 4;
                *(uint4*)&WH[off] = make_uint4(hw[0], hw[1], hw[2], hw[3]);
                *(uint4*)&WL[off] = make_uint4(lw[0], lw[1], lw[2], lw[3]);
            }
        }
        __syncthreads();
    }

    // ---- epilogue: stage C tile in smem (stride 132), coalesced writeout ----
    float* Cs = (float*)sm;
    #pragma unroll
    for (int mt = 0; mt < 2; mt++)
        #pragma unroll
        for (int nt = 0; nt < 8; nt++) {
            int r   = wm * 32 + mt * 16 + g;
            int col = wn * 64 + nt * 8 + tg * 2;
            Cs[r * 132 + col]           = c[mt][nt][0];
            Cs[r * 132 + col + 1]       = c[mt][nt][1];
            Cs[(r + 8) * 132 + col]     = c[mt][nt][2];
            Cs[(r + 8) * 132 + col + 1] = c[mt][nt][3];
        }
    __syncthreads();

    #pragma unroll 8
    for (int i = tid; i < 8192; i += 128) {
        int r = i >> 7, n = i & 127;
        float v = Cs[r * 132 + n];
        if (MODE == 1) {
            int m = m0 + r;
            float sc = __ldg(&gamma[m]) * rsqrtf(__ldg(&var[m]) + 1e-5f);
            v = v * sc + __ldg(&beta[m]) - __ldg(&mean[m]) * sc;
        }
        Cb[(size_t)(m0 + r) * HW + n0 + n] = v;
    }
}

// ---------------- fused p-mix + depthwise 3x3 (SAME, cross-correlation) -----
__global__ void __launch_bounds__(256)
pdw_kernel(const float* __restrict__ QKV,
           const float* __restrict__ Wp,
           const float* __restrict__ Wd,
           float* __restrict__ D)
{
    __shared__ float sin[8][4][WIDTH];
    __shared__ float sp [8][4][WIDTH];

    const int b  = blockIdx.z;
    const int gr = blockIdx.y;
    const int h0 = blockIdx.x * 2;
    const int tid = threadIdx.x;
    const float* src = QKV + ((size_t)b * CQKV + gr * 8) * HW;

    #pragma unroll
    for (int i = 0; i < 16; i++) {
        int lin = tid + i * 256;
        int ch = lin >> 9, rs = (lin >> 7) & 3, col = lin & 127;
        int row = h0 - 1 + rs;
        sin[ch][rs][col] = ((unsigned)row < (unsigned)WIDTH)
                           ? src[ch * HW + row * WIDTH + col] : 0.f;
    }
    __syncthreads();

    #pragma unroll
    for (int i = 0; i < 16; i++) {
        int lin = tid + i * 256;
        int oc = lin >> 9, rs = (lin >> 7) & 3, col = lin & 127;
        float s = 0.f;
        #pragma unroll
        for (int ic = 0; ic < 8; ic++)
            s += __ldg(&Wp[gr * 64 + oc * 8 + ic]) * sin[ic][rs][col];
        sp[oc][rs][col] = s;
    }
    __syncthreads();

    #pragma unroll
    for (int i = 0; i < 8; i++) {
        int lin = tid + i * 256;
        int oc = lin >> 8, hr = (lin >> 7) & 1, col = lin & 127;
        int c = gr * 8 + oc;
        float s = 0.f;
        #pragma unroll
        for (int ky = 0; ky < 3; ky++) {
            float w0 = __ldg(&Wd[c * 9 + ky * 3 + 0]);
            float w1 = __ldg(&Wd[c * 9 + ky * 3 + 1]);
            float w2 = __ldg(&Wd[c * 9 + ky * 3 + 2]);
            const float* row = sp[oc][hr + ky];
            if (col > 0)   s += w0 * row[col - 1];
            s += w1 * row[col];
            if (col < 127) s += w2 * row[col + 1];
        }
        D[((size_t)b * CQKV + c) * HW + (h0 + hr) * WIDTH + col] = s;
    }
}

// ---------------- kv partial sums: kv[b,G] = sum_n relu(k) outer [v|1] ------
__global__ void __launch_bounds__(256)
kv_kernel(const float* __restrict__ QKV,
          const float* __restrict__ D,
          float* __restrict__ kvp)
{
    const int b = blockIdx.z, G = blockIdx.y, chunk = blockIdx.x;
    const int tid = threadIdx.x;
    const float* base = (G < 8) ? QKV + ((size_t)b * CQKV + G * 24) * HW
                                : D   + ((size_t)b * CQKV + (G - 8) * 24) * HW;
    float acc[72];
    #pragma unroll
    for (int i = 0; i < 72; i++) acc[i] = 0.f;

    #pragma unroll
    for (int it = 0; it < 4; it++) {
        int n = chunk * 2048 + it * 512 + tid * 2;
        float2 kr[8], vr[8];
        #pragma unroll
        for (int d = 0; d < 8; d++) {
            float2 t = *(const float2*)&base[(8 + d) * HW + n];
            kr[d].x = fmaxf(t.x, 0.f); kr[d].y = fmaxf(t.y, 0.f);
        }
        #pragma unroll
        for (int e = 0; e < 8; e++) vr[e] = *(const float2*)&base[(16 + e) * HW + n];
        #pragma unroll
        for (int d = 0; d < 8; d++) {
            #pragma unroll
            for (int e = 0; e < 8; e++)
                acc[d * 9 + e] += kr[d].x * vr[e].x + kr[d].y * vr[e].y;
            acc[d * 9 + 8] += kr[d].x + kr[d].y;
        }
    }

    __shared__ float red[8][72];
    const int lane = tid & 31, warp = tid >> 5;
    #pragma unroll
    for (int i = 0; i < 72; i++) {
        float v = acc[i];
        #pragma unroll
        for (int off = 16; off; off >>= 1) v += __shfl_down_sync(0xffffffffu, v, off);
        if (lane == 0) red[warp][i] = v;
    }
    __syncthreads();
    for (int i = tid; i < 72; i += 256) {
        float s = 0.f;
        #pragma unroll
        for (int w2 = 0; w2 < 8; w2++) s += red[w2][i];
        kvp[((size_t)(b * 16 + G) * 8 + chunk) * 72 + i] = s;
    }
}

__global__ void kv_reduce(const float* __restrict__ kvp, float* __restrict__ kv)
{
    int i = blockIdx.x * 256 + threadIdx.x;
    int bg = i / 72, j = i % 72;
    float s = 0.f;
    #pragma unroll
    for (int c = 0; c < 8; c++) s += kvp[((size_t)bg * 8 + c) * 72 + j];
    kv[i] = s;
}

// ---------------- o = normalize(relu(q) @ kv), stored channel-major ---------
__global__ void __launch_bounds__(256)
o_kernel(const float* __restrict__ QKV,
         const float* __restrict__ D,
         const float* __restrict__ kv,
         float* __restrict__ O)
{
    const int b = blockIdx.y;
    __shared__ float skv[16 * 72];
    for (int i = threadIdx.x; i < 16 * 72; i += 256) skv[i] = kv[b * 16 * 72 + i];
    __syncthreads();

    const int n = blockIdx.x * 256 + threadIdx.x;
    #pragma unroll
    for (int G = 0; G < 16; G++) {
        const float* base = (G < 8) ? QKV + ((size_t)b * CQKV + G * 24) * HW
                                    : D   + ((size_t)b * CQKV + (G - 8) * 24) * HW;
        float num[8] = {};
        float den = 0.f;
        #pragma unroll
        for (int d = 0; d < 8; d++) {
            float q = fmaxf(base[d * HW + n], 0.f);
            #pragma unroll
            for (int j = 0; j < 8; j++) num[j] += q * skv[G * 72 + d * 9 + j];
            den += q * skv[G * 72 + d * 9 + 8];
        }
        float inv = 1.f / (den + 1e-15f);
        #pragma unroll
        for (int j = 0; j < 8; j++)
            O[((size_t)b * 128 + G * 8 + j) * HW + n] = num[j] * inv;
    }
}

// ---------------- launch --------------------------------------------------
extern "C" void kernel_launch(void* const* d_in, const int* in_sizes, int n_in,
                              void* d_out, int out_size)
{
    const float* x     = (const float*)d_in[0];
    const float* W_qkv = (const float*)d_in[1];
    const float* W_p   = (const float*)d_in[2];
    const float* W_d   = (const float*)d_in[3];
    const float* W_ffn = (const float*)d_in[4];
    const float* gamma = (const float*)d_in[5];
    const float* beta  = (const float*)d_in[6];
    const float* mean  = (const float*)d_in[7];
    const float* var   = (const float*)d_in[8];
    float* out = (float*)d_out;

    float *qkv, *d, *o, *kvp, *kv;
    cudaGetSymbolAddress((void**)&qkv, g_qkv);
    cudaGetSymbolAddress((void**)&d,   g_d);
    cudaGetSymbolAddress((void**)&o,   g_o);
    cudaGetSymbolAddress((void**)&kvp, g_kvp);
    cudaGetSymbolAddress((void**)&kv,  g_kv);

    // dynamic smem: qkv: 2*64*136*4 + 2*2*2176*4 = 104448 B
    //               ffn: 2*64*72*4  + 2*2*2176*4 =  71680 B
    const int SM_QKV = 2 * 64 * 136 * 4 + 4 * 2176 * 4;
    const int SM_FFN = 2 * 64 * 72 * 4 + 4 * 2176 * 4;
    cudaFuncSetAttribute(hgemm<256, 0>, cudaFuncAttributeMaxDynamicSharedMemorySize, SM_QKV);
    cudaFuncSetAttribute(hgemm<128, 1>, cudaFuncAttributeMaxDynamicSharedMemorySize, SM_FFN);

    // 1) qkv = W_qkv @ x
    hgemm<256, 0><<<dim3(HW / 128, CQKV / 64, NB), 128, SM_QKV>>>(
        W_qkv, x, qkv, CQKV, nullptr, nullptr, nullptr, nullptr);

    // 2) d = depthwise3x3(blockdiag(W_p) @ qkv)
    pdw_kernel<<<dim3(WIDTH / 2, 24, NB), 256>>>(qkv, W_p, W_d, d);

    // 3) kv reduction (two-stage, deterministic)
    kv_kernel<<<dim3(8, 16, NB), 256>>>(qkv, d, kvp);
    kv_reduce<<<(NB * 16 * 72) / 256, 256>>>(kvp, kv);

    // 4) o = normalize(relu(q) @ kv)
    o_kernel<<<dim3(HW / 256, NB), 256>>>(qkv, d, kv, o);

    // 5) out = BN(W_ffn @ o)
    hgemm<128, 1><<<dim3(HW / 128, 256 / 64, NB), 128, SM_FFN>>>(
        W_ffn, o, out, 256, gamma, beta, mean, var);
}

// round 7
// speedup vs baseline: 1.5360x; 1.5360x over previous
#include <cuda_runtime.h>
#include <cuda_bf16.h>
#include <math.h>
#include <stdint.h>

#define HW    16384
#define WIDTH 128
#define NB    8
#define CQKV  192

// ---------------- scratch (static device allocations; no cudaMalloc) --------
__device__ float    g_qkv[NB * CQKV * HW];    // 100.7 MB
__device__ float    g_d  [NB * CQKV * HW];    // 100.7 MB
__device__ uint32_t g_xh [NB * 128 * HW];     // x packed bf16-pair hi (67 MB)
__device__ uint32_t g_xl [NB * 128 * HW];     // x packed bf16-pair lo
__device__ uint32_t g_oh [NB * 64 * HW];      // o packed hi (33.5 MB)
__device__ uint32_t g_ol [NB * 64 * HW];      // o packed lo
__device__ uint32_t g_wqh[CQKV * 128], g_wql[CQKV * 128];
__device__ uint32_t g_wfh[256 * 64],   g_wfl[256 * 64];
__device__ float    g_kvp[NB * 16 * 8 * 72];
__device__ float    g_kv [NB * 16 * 72];

// ---------------- bf16 helpers ----------------------------------------------
__device__ __forceinline__ void bsplit(float x, float& h, float& l) {
    h = __bfloat162float(__float2bfloat16_rn(x));
    l = x - h;
}
__device__ __forceinline__ uint32_t bpack(float a, float b) {
    __nv_bfloat162 t = __floats2bfloat162_rn(a, b);   // .x = a (low), .y = b (high)
    return *reinterpret_cast<uint32_t*>(&t);
}
__device__ __forceinline__ void mma_bf16(float c[4], const uint32_t a[4], const uint32_t b[2]) {
    asm volatile(
        "mma.sync.aligned.m16n8k16.row.col.f32.bf16.bf16.f32 "
        "{%0,%1,%2,%3}, {%4,%5,%6,%7}, {%8,%9}, {%0,%1,%2,%3};\n"
        : "+f"(c[0]), "+f"(c[1]), "+f"(c[2]), "+f"(c[3])
        : "r"(a[0]), "r"(a[1]), "r"(a[2]), "r"(a[3]), "r"(b[0]), "r"(b[1]));
}
__device__ __forceinline__ uint32_t smem_u32(const void* p) {
    uint32_t a;
    asm("{ .reg .u64 t; cvta.to.shared.u64 t, %1; cvt.u32.u64 %0, t; }" : "=r"(a) : "l"(p));
    return a;
}
__device__ __forceinline__ void cpa16(uint32_t dst, const void* src) {
    asm volatile("cp.async.cg.shared.global [%0], [%1], 16;\n" :: "r"(dst), "l"(src));
}
#define CPA_COMMIT() asm volatile("cp.async.commit_group;\n" ::: "memory")
#define CPA_WAIT1()  asm volatile("cp.async.wait_group 1;\n" ::: "memory")
#define CPA_WAIT0()  asm volatile("cp.async.wait_group 0;\n" ::: "memory")

// ---------------- split kernels ---------------------------------------------
// W row-major MxK: k-pairs are contiguous -> trivial
__global__ void wsplit_kernel(const float* __restrict__ W,
                              uint32_t* __restrict__ WH, uint32_t* __restrict__ WL,
                              int npairs)
{
    int i = blockIdx.x * 256 + threadIdx.x;
    if (i >= npairs) return;
    float a = W[2 * i], b = W[2 * i + 1];
    float ha, la, hb, lb;
    bsplit(a, ha, la); bsplit(b, hb, lb);
    WH[i] = bpack(ha, hb);
    WL[i] = bpack(la, lb);
}

// X [b][K][HW] -> packed k-pair arrays [b][K/2][HW] (pair = rows 2kp, 2kp+1)
__global__ void xsplit_kernel(const float* __restrict__ X,
                              uint32_t* __restrict__ XH, uint32_t* __restrict__ XL)
{
    int idx = blockIdx.x * 256 + threadIdx.x;     // NB*128*(HW/4) float4 strips
    int n  = (idx & 4095) * 4;
    int t  = idx >> 12;                           // b*128 + kp
    const float4 a = *(const float4*)&X[(size_t)t * 2 * HW + n];
    const float4 b = *(const float4*)&X[(size_t)t * 2 * HW + HW + n];
    const float av[4] = {a.x, a.y, a.z, a.w};
    const float bv[4] = {b.x, b.y, b.z, b.w};
    uint32_t hw[4], lw[4];
    #pragma unroll
    for (int j = 0; j < 4; j++) {
        float ha, la, hb, lb;
        bsplit(av[j], ha, la); bsplit(bv[j], hb, lb);
        hw[j] = bpack(ha, hb); lw[j] = bpack(la, lb);
    }
    *(uint4*)&XH[(size_t)t * HW + n] = make_uint4(hw[0], hw[1], hw[2], hw[3]);
    *(uint4*)&XL[(size_t)t * HW + n] = make_uint4(lw[0], lw[1], lw[2], lw[3]);
}

// ============ bf16x3 HMMA GEMM on pre-split operands ========================
// C[b](M x HW) = W(M x KTOT) * X[b](KTOT x HW)
// Block 64(M) x 64(N), 128 threads (4 warps, 32x32 warp tiles), k32 chunks,
// double-buffered cp.async stages. Mainloop: cp.async + LDS + HMMA only.
// MODE 0: plain store. MODE 1: batchnorm affine on channel (row).
template <int KTOT, int MODE>
__global__ void __launch_bounds__(128)
hgemm(const uint32_t* __restrict__ AH, const uint32_t* __restrict__ AL,
      const uint32_t* __restrict__ BHg, const uint32_t* __restrict__ BLg,
      float* __restrict__ C, int M,
      const float* __restrict__ gamma, const float* __restrict__ beta,
      const float* __restrict__ mean,  const float* __restrict__ var)
{
    constexpr int KP   = KTOT / 2;
    constexpr int NKIT = KTOT / 32;
    constexpr int SWRD = 4864;            // words per stage: 2*1280 + 2*1152

    __shared__ uint32_t sm[2 * SWRD];     // 38912 B
    const uint32_t smb = smem_u32(sm);

    const int tid  = threadIdx.x;
    const int lane = tid & 31;
    const int warp = tid >> 5;
    const int wm   = warp >> 1;
    const int wn   = warp & 1;
    const int g    = lane >> 2;
    const int tg   = lane & 3;

    const int m0 = blockIdx.y * 64;
    const int n0 = blockIdx.x * 64;
    const uint32_t* Bh = BHg + (size_t)blockIdx.z * KP * HW;
    const uint32_t* Bl = BLg + (size_t)blockIdx.z * KP * HW;
    float*          Cb = C   + (size_t)blockIdx.z * M * HW;

    // loader roles
    const int arow = tid >> 1, aq = (tid & 1) * 8;      // A: 64 rows, 8-word halves
    const int brow = tid >> 3, bs = (tid & 7) * 8;      // B: 16 kp-rows, 8-word segs

    auto load_chunk = [&](int it, int stage) {
        const uint32_t s0 = smb + stage * SWRD * 4;
        // A: 64 rows x 16 words per chunk per half; thread covers 8 words
        const uint32_t* srcAh = AH + (size_t)(m0 + arow) * KP + it * 16 + aq;
        const uint32_t* srcAl = AL + (size_t)(m0 + arow) * KP + it * 16 + aq;
        uint32_t dA = s0 + (arow * 20 + aq) * 4;
        cpa16(dA,                 srcAh);
        cpa16(dA + 16,            srcAh + 4);
        cpa16(dA + 1280 * 4,      srcAl);
        cpa16(dA + 1280 * 4 + 16, srcAl + 4);
        // B: 16 kp-rows x 64 words per half; thread covers 8 words
        const uint32_t* srcBh = Bh + (size_t)(it * 16 + brow) * HW + n0 + bs;
        const uint32_t* srcBl = Bl + (size_t)(it * 16 + brow) * HW + n0 + bs;
        uint32_t dB = s0 + (2560 + brow * 72 + bs) * 4;
        cpa16(dB,                 srcBh);
        cpa16(dB + 16,            srcBh + 4);
        cpa16(dB + 1152 * 4,      srcBl);
        cpa16(dB + 1152 * 4 + 16, srcBl + 4);
    };

    load_chunk(0, 0);
    CPA_COMMIT();

    float c[2][4][4] = {};

    for (int it = 0; it < NKIT; it++) {
        if (it + 1 < NKIT) { load_chunk(it + 1, (it + 1) & 1); CPA_COMMIT(); CPA_WAIT1(); }
        else               { CPA_WAIT0(); }
        __syncthreads();

        const uint32_t* sAh = sm + (it & 1) * SWRD;
        const uint32_t* sAl = sAh + 1280;
        const uint32_t* sBh = sAh + 2560;
        const uint32_t* sBl = sAh + 3712;

        #pragma unroll
        for (int ks = 0; ks < 2; ks++) {
            const int kp0 = ks * 8;
            uint32_t ah[2][4], al[2][4], bh[4][2], bl[4][2];
            #pragma unroll
            for (int mt = 0; mt < 2; mt++) {
                int r = wm * 32 + mt * 16 + g;
                ah[mt][0] = sAh[r * 20 + kp0 + tg];
                ah[mt][1] = sAh[(r + 8) * 20 + kp0 + tg];
                ah[mt][2] = sAh[r * 20 + kp0 + tg + 4];
                ah[mt][3] = sAh[(r + 8) * 20 + kp0 + tg + 4];
                al[mt][0] = sAl[r * 20 + kp0 + tg];
                al[mt][1] = sAl[(r + 8) * 20 + kp0 + tg];
                al[mt][2] = sAl[r * 20 + kp0 + tg + 4];
                al[mt][3] = sAl[(r + 8) * 20 + kp0 + tg + 4];
            }
            #pragma unroll
            for (int nt = 0; nt < 4; nt++) {
                int col = wn * 32 + nt * 8 + g;
                bh[nt][0] = sBh[(kp0 + tg) * 72 + col];
                bh[nt][1] = sBh[(kp0 + tg + 4) * 72 + col];
                bl[nt][0] = sBl[(kp0 + tg) * 72 + col];
                bl[nt][1] = sBl[(kp0 + tg + 4) * 72 + col];
            }
            // pass-wise: hh, hl, lh (8 independent accumulators per pass)
            #pragma unroll
            for (int nt = 0; nt < 4; nt++)
                #pragma unroll
                for (int mt = 0; mt < 2; mt++) mma_bf16(c[mt][nt], ah[mt], bh[nt]);
            #pragma unroll
            for (int nt = 0; nt < 4; nt++)
                #pragma unroll
                for (int mt = 0; mt < 2; mt++) mma_bf16(c[mt][nt], ah[mt], bl[nt]);
            #pragma unroll
            for (int nt = 0; nt < 4; nt++)
                #pragma unroll
                for (int mt = 0; mt < 2; mt++) mma_bf16(c[mt][nt], al[mt], bh[nt]);
        }
        __syncthreads();
    }

    // ---- epilogue: stage C tile in smem (stride 68), coalesced writeout ----
    float* Cs = (float*)sm;
    #pragma unroll
    for (int mt = 0; mt < 2; mt++)
        #pragma unroll
        for (int nt = 0; nt < 4; nt++) {
            int r   = wm * 32 + mt * 16 + g;
            int col = wn * 32 + nt * 8 + tg * 2;
            Cs[r * 68 + col]           = c[mt][nt][0];
            Cs[r * 68 + col + 1]       = c[mt][nt][1];
            Cs[(r + 8) * 68 + col]     = c[mt][nt][2];
            Cs[(r + 8) * 68 + col + 1] = c[mt][nt][3];
        }
    __syncthreads();

    #pragma unroll 8
    for (int i = tid; i < 4096; i += 128) {
        int r = i >> 6, n = i & 63;
        float v = Cs[r * 68 + n];
        if (MODE == 1) {
            int m = m0 + r;
            float sc = __ldg(&gamma[m]) * rsqrtf(__ldg(&var[m]) + 1e-5f);
            v = v * sc + __ldg(&beta[m]) - __ldg(&mean[m]) * sc;
        }
        Cb[(size_t)(m0 + r) * HW + n0 + n] = v;
    }
}

// ---------------- fused p-mix + depthwise 3x3 (SAME, cross-correlation) -----
__global__ void __launch_bounds__(256)
pdw_kernel(const float* __restrict__ QKV,
           const float* __restrict__ Wp,
           const float* __restrict__ Wd,
           float* __restrict__ D)
{
    __shared__ float sin[8][4][WIDTH];
    __shared__ float sp [8][4][WIDTH];

    const int b  = blockIdx.z;
    const int gr = blockIdx.y;
    const int h0 = blockIdx.x * 2;
    const int tid = threadIdx.x;
    const float* src = QKV + ((size_t)b * CQKV + gr * 8) * HW;

    #pragma unroll
    for (int i = 0; i < 16; i++) {
        int lin = tid + i * 256;
        int ch = lin >> 9, rs = (lin >> 7) & 3, col = lin & 127;
        int row = h0 - 1 + rs;
        sin[ch][rs][col] = ((unsigned)row < (unsigned)WIDTH)
                           ? src[ch * HW + row * WIDTH + col] : 0.f;
    }
    __syncthreads();

    #pragma unroll
    for (int i = 0; i < 16; i++) {
        int lin = tid + i * 256;
        int oc = lin >> 9, rs = (lin >> 7) & 3, col = lin & 127;
        float s = 0.f;
        #pragma unroll
        for (int ic = 0; ic < 8; ic++)
            s += __ldg(&Wp[gr * 64 + oc * 8 + ic]) * sin[ic][rs][col];
        sp[oc][rs][col] = s;
    }
    __syncthreads();

    #pragma unroll
    for (int i = 0; i < 8; i++) {
        int lin = tid + i * 256;
        int oc = lin >> 8, hr = (lin >> 7) & 1, col = lin & 127;
        int c = gr * 8 + oc;
        float s = 0.f;
        #pragma unroll
        for (int ky = 0; ky < 3; ky++) {
            float w0 = __ldg(&Wd[c * 9 + ky * 3 + 0]);
            float w1 = __ldg(&Wd[c * 9 + ky * 3 + 1]);
            float w2 = __ldg(&Wd[c * 9 + ky * 3 + 2]);
            const float* row = sp[oc][hr + ky];
            if (col > 0)   s += w0 * row[col - 1];
            s += w1 * row[col];
            if (col < 127) s += w2 * row[col + 1];
        }
        D[((size_t)b * CQKV + c) * HW + (h0 + hr) * WIDTH + col] = s;
    }
}

// ---------------- kv partial sums -------------------------------------------
__global__ void __launch_bounds__(256)
kv_kernel(const float* __restrict__ QKV,
          const float* __restrict__ D,
          float* __restrict__ kvp)
{
    const int b = blockIdx.z, G = blockIdx.y, chunk = blockIdx.x;
    const int tid = threadIdx.x;
    const float* base = (G < 8) ? QKV + ((size_t)b * CQKV + G * 24) * HW
                                : D   + ((size_t)b * CQKV + (G - 8) * 24) * HW;
    float acc[72];
    #pragma unroll
    for (int i = 0; i < 72; i++) acc[i] = 0.f;

    #pragma unroll
    for (int it = 0; it < 4; it++) {
        int n = chunk * 2048 + it * 512 + tid * 2;
        float2 kr[8], vr[8];
        #pragma unroll
        for (int d = 0; d < 8; d++) {
            float2 t = *(const float2*)&base[(8 + d) * HW + n];
            kr[d].x = fmaxf(t.x, 0.f); kr[d].y = fmaxf(t.y, 0.f);
        }
        #pragma unroll
        for (int e = 0; e < 8; e++) vr[e] = *(const float2*)&base[(16 + e) * HW + n];
        #pragma unroll
        for (int d = 0; d < 8; d++) {
            #pragma unroll
            for (int e = 0; e < 8; e++)
                acc[d * 9 + e] += kr[d].x * vr[e].x + kr[d].y * vr[e].y;
            acc[d * 9 + 8] += kr[d].x + kr[d].y;
        }
    }

    __shared__ float red[8][72];
    const int lane = tid & 31, warp = tid >> 5;
    #pragma unroll
    for (int i = 0; i < 72; i++) {
        float v = acc[i];
        #pragma unroll
        for (int off = 16; off; off >>= 1) v += __shfl_down_sync(0xffffffffu, v, off);
        if (lane == 0) red[warp][i] = v;
    }
    __syncthreads();
    for (int i = tid; i < 72; i += 256) {
        float s = 0.f;
        #pragma unroll
        for (int w2 = 0; w2 < 8; w2++) s += red[w2][i];
        kvp[((size_t)(b * 16 + G) * 8 + chunk) * 72 + i] = s;
    }
}

__global__ void kv_reduce(const float* __restrict__ kvp, float* __restrict__ kv)
{
    int i = blockIdx.x * 256 + threadIdx.x;
    int bg = i / 72, j = i % 72;
    float s = 0.f;
    #pragma unroll
    for (int c = 0; c < 8; c++) s += kvp[((size_t)bg * 8 + c) * 72 + j];
    kv[i] = s;
}

// ------- o = normalize(relu(q)@kv), written as packed bf16 hi/lo pairs ------
__global__ void __launch_bounds__(256)
o_kernel(const float* __restrict__ QKV,
         const float* __restrict__ D,
         const float* __restrict__ kv,
         uint32_t* __restrict__ OH,
         uint32_t* __restrict__ OL)
{
    const int b = blockIdx.y;
    __shared__ float skv[16 * 72];
    for (int i = threadIdx.x; i < 16 * 72; i += 256) skv[i] = kv[b * 16 * 72 + i];
    __syncthreads();

    const int n = blockIdx.x * 256 + threadIdx.x;
    #pragma unroll
    for (int G = 0; G < 16; G++) {
        const float* base = (G < 8) ? QKV + ((size_t)b * CQKV + G * 24) * HW
                                    : D   + ((size_t)b * CQKV + (G - 8) * 24) * HW;
        float num[8] = {};
        float den = 0.f;
        #pragma unroll
        for (int d = 0; d < 8; d++) {
            float q = fmaxf(base[d * HW + n], 0.f);
            #pragma unroll
            for (int j = 0; j < 8; j++) num[j] += q * skv[G * 72 + d * 9 + j];
            den += q * skv[G * 72 + d * 9 + 8];
        }
        float inv = 1.f / (den + 1e-15f);
        #pragma unroll
        for (int jj = 0; jj < 4; jj++) {
            float v0 = num[2 * jj] * inv, v1 = num[2 * jj + 1] * inv;
            float h0, l0, h1, l1;
            bsplit(v0, h0, l0); bsplit(v1, h1, l1);
            size_t o = ((size_t)b * 64 + G * 4 + jj) * HW + n;
            OH[o] = bpack(h0, h1);
            OL[o] = bpack(l0, l1);
        }
    }
}

// ---------------- launch --------------------------------------------------
extern "C" void kernel_launch(void* const* d_in, const int* in_sizes, int n_in,
                              void* d_out, int out_size)
{
    const float* x     = (const float*)d_in[0];
    const float* W_qkv = (const float*)d_in[1];
    const float* W_p   = (const float*)d_in[2];
    const float* W_d   = (const float*)d_in[3];
    const float* W_ffn = (const float*)d_in[4];
    const float* gamma = (const float*)d_in[5];
    const float* beta  = (const float*)d_in[6];
    const float* mean  = (const float*)d_in[7];
    const float* var   = (const float*)d_in[8];
    float* out = (float*)d_out;

    float *qkv, *d, *kvp, *kv;
    uint32_t *xh, *xl, *oh, *ol, *wqh, *wql, *wfh, *wfl;
    cudaGetSymbolAddress((void**)&qkv, g_qkv);
    cudaGetSymbolAddress((void**)&d,   g_d);
    cudaGetSymbolAddress((void**)&xh,  g_xh);
    cudaGetSymbolAddress((void**)&xl,  g_xl);
    cudaGetSymbolAddress((void**)&oh,  g_oh);
    cudaGetSymbolAddress((void**)&ol,  g_ol);
    cudaGetSymbolAddress((void**)&wqh, g_wqh);
    cudaGetSymbolAddress((void**)&wql, g_wql);
    cudaGetSymbolAddress((void**)&wfh, g_wfh);
    cudaGetSymbolAddress((void**)&wfl, g_wfl);
    cudaGetSymbolAddress((void**)&kvp, g_kvp);
    cudaGetSymbolAddress((void**)&kv,  g_kv);

    // 0) operand conversions (once per call)
    wsplit_kernel<<<(CQKV * 128 + 255) / 256, 256>>>(W_qkv, wqh, wql, CQKV * 128);
    wsplit_kernel<<<(256 * 64 + 255) / 256, 256>>>(W_ffn, wfh, wfl, 256 * 64);
    xsplit_kernel<<<NB * 128 * (HW / 4) / 256, 256>>>(x, xh, xl);

    // 1) qkv = W_qkv @ x  (bf16x3 HMMA, pre-split)
    hgemm<256, 0><<<dim3(HW / 64, CQKV / 64, NB), 128>>>(
        wqh, wql, xh, xl, qkv, CQKV, nullptr, nullptr, nullptr, nullptr);

    // 2) d = depthwise3x3(blockdiag(W_p) @ qkv)
    pdw_kernel<<<dim3(WIDTH / 2, 24, NB), 256>>>(qkv, W_p, W_d, d);

    // 3) kv reduction (two-stage, deterministic)
    kv_kernel<<<dim3(8, 16, NB), 256>>>(qkv, d, kvp);
    kv_reduce<<<(NB * 16 * 72) / 256, 256>>>(kvp, kv);

    // 4) o = normalize(relu(q) @ kv) -> packed bf16 hi/lo pairs
    o_kernel<<<dim3(HW / 256, NB), 256>>>(qkv, d, kv, oh, ol);

    // 5) out = BN(W_ffn @ o)
    hgemm<128, 1><<<dim3(HW / 64, 256 / 64, NB), 128>>>(
        wfh, wfl, oh, ol, out, 256, gamma, beta, mean, var);
}